// round 1
// baseline (speedup 1.0000x reference)
#include <cuda_runtime.h>
#include <math.h>

// NeRF fused renderer: B=1, N=4096 rays, S=128 samples, H=256.
// One CTA per ray. h1 in SMEM, W2 staged in 64-row chunks, h2 never
// materialized (fused relu + sigma/rgb projections in the GEMM epilogue).

namespace {
constexpr int S_   = 128;
constexpr int H_   = 256;
constexpr float NEARV = 0.1f;
constexpr float FARV  = 4.0f;
constexpr float EPSV  = 1e-6f;
constexpr int STRIDE  = 129;   // padded h1 row stride (conflict-free)
constexpr int KC      = 64;    // W2 k-chunk rows staged per stage
// smem: h1s[256][129] + w2s[64][128] (aliased as red[4][16][128]) + cbuf[4][128]
constexpr int SMEM_FLOATS = H_ * STRIDE + KC * 128 + 4 * 128;
}

__global__ __launch_bounds__(256, 1)
void nerf_fused_kernel(const float* __restrict__ cam,
                       const float* __restrict__ rayv,
                       const float* __restrict__ W1,
                       const float* __restrict__ b1,
                       const float* __restrict__ W2,
                       const float* __restrict__ b2,
                       const float* __restrict__ Wsig,
                       const float* __restrict__ bsig,
                       const float* __restrict__ Wrgb,
                       const float* __restrict__ brgb,
                       float* __restrict__ out)
{
    extern __shared__ float sm[];
    float* h1s  = sm;                 // [256][129]  layer-1 activations (k-major)
    float* w2s  = sm + H_ * STRIDE;   // [64][128]   W2 chunk; later red[4][16][128]
    float* cbuf = w2s + KC * 128;     // [4][128]    alpha, rgb for composite

    const int r   = blockIdx.x;
    const int tid = threadIdx.x;
    const int tx  = tid & 15;         // point-group index (8 pts, stride 16)
    const int ty  = tid >> 4;         // j-group index (8 j's, stride 16)

    // ---- per-ray geometry (all threads, redundant & cheap) ----
    const float c0 = cam[r*3+0], c1 = cam[r*3+1], c2 = cam[r*3+2];
    const float v0 = rayv[r*3+0], v1 = rayv[r*3+1], v2 = rayv[r*3+2];
    const float inv = rsqrtf(v0*v0 + v1*v1 + v2*v2);
    const float d0 = v0*inv, d1 = v1*inv, d2 = v2*inv;

    // ---- layer 1: h1[k][p] = relu(b1 + (cam.W1col) + (rd.W1col)*z_p) ----
    {
        const int k = tid;
        const float w0 = W1[k], w1 = W1[H_ + k], w2 = W1[2*H_ + k];
        const float ac = c0*w0 + c1*w1 + c2*w2 + b1[k];
        const float bc = d0*w0 + d1*w1 + d2*w2;
        float* row = h1s + k * STRIDE;
        #pragma unroll 4
        for (int p = 0; p < S_; ++p) {
            float t = (float)p * (1.0f / 127.0f);
            float z = NEARV * (1.0f - t) + FARV * t;
            row[p] = fmaxf(fmaf(bc, z, ac), 0.0f);
        }
    }

    // ---- hidden GEMM + fused heads ----
    float psig[8];
    float prgb[8][3];
    #pragma unroll
    for (int i = 0; i < 8; ++i) {
        psig[i] = 0.f; prgb[i][0] = 0.f; prgb[i][1] = 0.f; prgb[i][2] = 0.f;
    }

    for (int jb = 0; jb < 2; ++jb) {
        float acc[8][8];
        #pragma unroll
        for (int i = 0; i < 8; ++i)
            #pragma unroll
            for (int j = 0; j < 8; ++j) acc[i][j] = 0.f;

        for (int kc = 0; kc < H_; kc += KC) {
            __syncthreads();
            // stage W2 rows [kc, kc+64) x cols [jb*128, +128), coalesced float4
            #pragma unroll
            for (int idx = tid; idx < KC * 32; idx += 256) {
                int row = idx >> 5, c4 = idx & 31;
                float4 v = *(const float4*)(W2 + (kc + row) * H_ + jb * 128 + c4 * 4);
                *(float4*)(w2s + row * 128 + c4 * 4) = v;
            }
            __syncthreads();
            #pragma unroll 4
            for (int kk = 0; kk < KC; ++kk) {
                const float* arow = h1s + (kc + kk) * STRIDE + tx;
                const float* brow = w2s + kk * 128 + ty;
                float a[8], b[8];
                #pragma unroll
                for (int i = 0; i < 8; ++i) a[i] = arow[16 * i];
                #pragma unroll
                for (int j = 0; j < 8; ++j) b[j] = brow[16 * j];
                #pragma unroll
                for (int i = 0; i < 8; ++i)
                    #pragma unroll
                    for (int j = 0; j < 8; ++j)
                        acc[i][j] = fmaf(a[i], b[j], acc[i][j]);
            }
        }

        // fused epilogue: relu(h2) projected onto Wsig / Wrgb[:256]
        #pragma unroll
        for (int jj = 0; jj < 8; ++jj) {
            int j = jb * 128 + ty + 16 * jj;
            float b2v = b2[j];
            float wsv = Wsig[j];
            float wr0 = Wrgb[j*3+0], wr1 = Wrgb[j*3+1], wr2 = Wrgb[j*3+2];
            #pragma unroll
            for (int i = 0; i < 8; ++i) {
                float h = fmaxf(acc[i][jj] + b2v, 0.0f);
                psig[i]    = fmaf(h, wsv, psig[i]);
                prgb[i][0] = fmaf(h, wr0, prgb[i][0]);
                prgb[i][1] = fmaf(h, wr1, prgb[i][1]);
                prgb[i][2] = fmaf(h, wr2, prgb[i][2]);
            }
        }
    }

    // ---- deterministic reduction over the 16 j-groups ----
    __syncthreads();                  // everyone done reading w2s
    float* red = w2s;                 // alias: [4][16][128]
    #pragma unroll
    for (int i = 0; i < 8; ++i) {
        int p = tx + 16 * i;
        red[0*2048 + ty*128 + p] = psig[i];
        red[1*2048 + ty*128 + p] = prgb[i][0];
        red[2*2048 + ty*128 + p] = prgb[i][1];
        red[3*2048 + ty*128 + p] = prgb[i][2];
    }
    __syncthreads();

    if (tid < S_) {
        float s0 = 0.f, s1 = 0.f, s2 = 0.f, s3 = 0.f;
        #pragma unroll
        for (int t = 0; t < 16; ++t) {
            s0 += red[0*2048 + t*128 + tid];
            s1 += red[1*2048 + t*128 + tid];
            s2 += red[2*2048 + t*128 + tid];
            s3 += red[3*2048 + t*128 + tid];
        }
        float sigma = fmaxf(s0 + bsig[0], 0.0f);

        float t0 = (float)tid * (1.0f / 127.0f);
        float z0 = NEARV * (1.0f - t0) + FARV * t0;
        float t1 = (float)(tid + 1) * (1.0f / 127.0f);
        float z1 = NEARV * (1.0f - t1) + FARV * t1;
        float alpha = (tid < S_ - 1) ? (1.0f - expf(-sigma * (z1 - z0))) : 1.0f;

        // view-dir rows of Wrgb (dirs = -rd, constant along the ray) + bias
        float e0 = brgb[0] - (d0*Wrgb[(H_+0)*3+0] + d1*Wrgb[(H_+1)*3+0] + d2*Wrgb[(H_+2)*3+0]);
        float e1 = brgb[1] - (d0*Wrgb[(H_+0)*3+1] + d1*Wrgb[(H_+1)*3+1] + d2*Wrgb[(H_+2)*3+1]);
        float e2 = brgb[2] - (d0*Wrgb[(H_+0)*3+2] + d1*Wrgb[(H_+1)*3+2] + d2*Wrgb[(H_+2)*3+2]);

        cbuf[tid]         = alpha;
        cbuf[128 + tid]   = 1.0f / (1.0f + expf(-(s1 + e0)));
        cbuf[256 + tid]   = 1.0f / (1.0f + expf(-(s2 + e1)));
        cbuf[384 + tid]   = 1.0f / (1.0f + expf(-(s3 + e2)));
    }
    __syncthreads();

    // ---- sequential composite (exclusive cumprod of (1 - a + eps)) ----
    if (tid == 0) {
        float T = 1.0f, o0 = 0.f, o1 = 0.f, o2 = 0.f;
        for (int s = 0; s < S_; ++s) {
            float a = cbuf[s];
            float w = a * T;
            o0 = fmaf(w, cbuf[128 + s], o0);
            o1 = fmaf(w, cbuf[256 + s], o1);
            o2 = fmaf(w, cbuf[384 + s], o2);
            T *= (1.0f - a + EPSV);
        }
        out[r*3 + 0] = o0;
        out[r*3 + 1] = o1;
        out[r*3 + 2] = o2;
    }
}

extern "C" void kernel_launch(void* const* d_in, const int* in_sizes, int n_in,
                              void* d_out, int out_size)
{
    const float* cam  = (const float*)d_in[0];
    const float* rayv = (const float*)d_in[1];
    const float* W1   = (const float*)d_in[2];
    const float* b1   = (const float*)d_in[3];
    const float* W2   = (const float*)d_in[4];
    const float* b2   = (const float*)d_in[5];
    const float* Wsig = (const float*)d_in[6];
    const float* bsig = (const float*)d_in[7];
    const float* Wrgb = (const float*)d_in[8];
    const float* brgb = (const float*)d_in[9];
    float* out = (float*)d_out;

    const int nrays = in_sizes[0] / 3;            // B*N = 4096
    const size_t smem = SMEM_FLOATS * sizeof(float);  // ~167 KB

    cudaFuncSetAttribute(nerf_fused_kernel,
                         cudaFuncAttributeMaxDynamicSharedMemorySize, (int)smem);
    nerf_fused_kernel<<<nrays, 256, smem>>>(cam, rayv, W1, b1, W2, b2,
                                            Wsig, bsig, Wrgb, brgb, out);
}

// round 2
// speedup vs baseline: 1.0913x; 1.0913x over previous
#include <cuda_runtime.h>
#include <math.h>

// NeRF fused renderer, R2: packed fp32x2 FMA (FFMA2) mainloop.
// One CTA per ray (4096 CTAs, 256 thr). h1 stored in SMEM as interleaved
// float2 pairs (p, p+64); W2 staged pre-duplicated (w,w) so both MMA
// operands arrive packed via LDS.64. 32 fma.rn.f32x2 per k-step per thread.

namespace {
constexpr int S_   = 128;
constexpr int H_   = 256;
constexpr float NEARV = 0.1f;
constexpr float FARV  = 4.0f;
constexpr float EPSV  = 1e-6f;
constexpr int HP_STRIDE = 65;   // h1p row stride in float2 (pad: 2-way max on STS)
constexpr int KC        = 64;   // W2 rows staged per chunk
// smem (floats): h1p 256*65*2 + w2d 64*128*2 + cbuf 4*128
constexpr int SMEM_FLOATS = H_ * HP_STRIDE * 2 + KC * 128 * 2 + 4 * 128;
}

__device__ __forceinline__ void ffma2(unsigned long long& d,
                                      unsigned long long a,
                                      unsigned long long b) {
    asm("fma.rn.f32x2 %0, %1, %2, %0;" : "+l"(d) : "l"(a), "l"(b));
}
__device__ __forceinline__ void unpack2(float& lo, float& hi, unsigned long long v) {
    asm("mov.b64 {%0, %1}, %2;" : "=f"(lo), "=f"(hi) : "l"(v));
}

__global__ __launch_bounds__(256, 1)
void nerf_fused_kernel(const float* __restrict__ cam,
                       const float* __restrict__ rayv,
                       const float* __restrict__ W1,
                       const float* __restrict__ b1,
                       const float* __restrict__ W2,
                       const float* __restrict__ b2,
                       const float* __restrict__ Wsig,
                       const float* __restrict__ bsig,
                       const float* __restrict__ Wrgb,
                       const float* __restrict__ brgb,
                       float* __restrict__ out)
{
    extern __shared__ float sm[];
    // h1p[k][q] = (h1[k][q], h1[k][q+64]),  q in [0,64), row stride HP_STRIDE
    unsigned long long* h1p = (unsigned long long*)sm;
    unsigned long long* w2d = h1p + H_ * HP_STRIDE;   // [64][128] dup pairs (w,w)
    float* red  = (float*)w2d;                        // alias after GEMM: [4][16][128]
    float* cbuf = (float*)(w2d + KC * 128);           // [4][128]

    const int r   = blockIdx.x;
    const int tid = threadIdx.x;
    const int tx  = tid & 15;         // point-pair group (4 pairs, stride 16)
    const int ty  = tid >> 4;         // j group (8 j's, stride 16)

    // ---- per-ray geometry ----
    const float c0 = cam[r*3+0], c1 = cam[r*3+1], c2 = cam[r*3+2];
    const float v0 = rayv[r*3+0], v1 = rayv[r*3+1], v2 = rayv[r*3+2];
    const float inv = rsqrtf(v0*v0 + v1*v1 + v2*v2);
    const float d0 = v0*inv, d1 = v1*inv, d2 = v2*inv;

    // ---- layer 1: h1[k][p] = relu(ac + bc * z_p), write interleaved pairs ----
    {
        const int k = tid;
        const float w0 = W1[k], w1 = W1[H_ + k], w2 = W1[2*H_ + k];
        const float ac = c0*w0 + c1*w1 + c2*w2 + b1[k];
        const float bc = d0*w0 + d1*w1 + d2*w2;
        float2* row = (float2*)(h1p + k * HP_STRIDE);
        #pragma unroll 4
        for (int q = 0; q < 64; ++q) {
            float za = NEARV + (FARV - NEARV) * ((float)q        * (1.0f / 127.0f));
            float zb = NEARV + (FARV - NEARV) * ((float)(q + 64) * (1.0f / 127.0f));
            row[q] = make_float2(fmaxf(fmaf(bc, za, ac), 0.0f),
                                 fmaxf(fmaf(bc, zb, ac), 0.0f));
        }
    }

    // ---- hidden GEMM (packed f32x2) + fused heads ----
    float psig[4][2];
    float prgb[4][2][3];
    #pragma unroll
    for (int i = 0; i < 4; ++i)
        #pragma unroll
        for (int h = 0; h < 2; ++h) {
            psig[i][h] = 0.f;
            prgb[i][h][0] = 0.f; prgb[i][h][1] = 0.f; prgb[i][h][2] = 0.f;
        }

    for (int jb = 0; jb < 2; ++jb) {
        unsigned long long acc[4][8];
        #pragma unroll
        for (int i = 0; i < 4; ++i)
            #pragma unroll
            for (int j = 0; j < 8; ++j) acc[i][j] = 0ULL;

        for (int kc = 0; kc < H_; kc += KC) {
            __syncthreads();
            // stage W2 rows [kc,kc+64) x cols [jb*128,+128), duplicated (w,w).
            // LDG.64 (two cols) -> STS.128 (two dup pairs), 16 iters/thread.
            #pragma unroll
            for (int it = 0; it < 16; ++it) {
                int idx = tid + it * 256;          // over 64*64 col-pairs
                int row = idx >> 6, cp = idx & 63;
                float2 v = *(const float2*)(W2 + (kc + row) * H_ + jb * 128 + cp * 2);
                *(float4*)(w2d + row * 128 + cp * 2) =
                    make_float4(v.x, v.x, v.y, v.y);
            }
            __syncthreads();
            #pragma unroll 4
            for (int kk = 0; kk < KC; ++kk) {
                const unsigned long long* arow = h1p + (kc + kk) * HP_STRIDE + tx;
                const unsigned long long* brow = w2d + kk * 128 + ty;
                unsigned long long a[4], b[8];
                #pragma unroll
                for (int i = 0; i < 4; ++i) a[i] = arow[16 * i];
                #pragma unroll
                for (int j = 0; j < 8; ++j) b[j] = brow[16 * j];
                #pragma unroll
                for (int i = 0; i < 4; ++i)
                    #pragma unroll
                    for (int j = 0; j < 8; ++j)
                        ffma2(acc[i][j], a[i], b[j]);
            }
        }

        // fused epilogue: relu(h2 + b2) projected onto Wsig / Wrgb[:256]
        #pragma unroll
        for (int jj = 0; jj < 8; ++jj) {
            int j = jb * 128 + ty + 16 * jj;
            float b2v = b2[j];
            float wsv = Wsig[j];
            float wr0 = Wrgb[j*3+0], wr1 = Wrgb[j*3+1], wr2 = Wrgb[j*3+2];
            #pragma unroll
            for (int i = 0; i < 4; ++i) {
                float lo, hi;
                unpack2(lo, hi, acc[i][jj]);
                float hl = fmaxf(lo + b2v, 0.0f);
                float hh = fmaxf(hi + b2v, 0.0f);
                psig[i][0]    = fmaf(hl, wsv, psig[i][0]);
                prgb[i][0][0] = fmaf(hl, wr0, prgb[i][0][0]);
                prgb[i][0][1] = fmaf(hl, wr1, prgb[i][0][1]);
                prgb[i][0][2] = fmaf(hl, wr2, prgb[i][0][2]);
                psig[i][1]    = fmaf(hh, wsv, psig[i][1]);
                prgb[i][1][0] = fmaf(hh, wr0, prgb[i][1][0]);
                prgb[i][1][1] = fmaf(hh, wr1, prgb[i][1][1]);
                prgb[i][1][2] = fmaf(hh, wr2, prgb[i][1][2]);
            }
        }
    }

    // ---- deterministic reduction over the 16 j-groups ----
    __syncthreads();                  // everyone done reading w2d
    #pragma unroll
    for (int i = 0; i < 4; ++i)
        #pragma unroll
        for (int h = 0; h < 2; ++h) {
            int p = tx + 16 * i + 64 * h;
            red[0*2048 + ty*128 + p] = psig[i][h];
            red[1*2048 + ty*128 + p] = prgb[i][h][0];
            red[2*2048 + ty*128 + p] = prgb[i][h][1];
            red[3*2048 + ty*128 + p] = prgb[i][h][2];
        }
    __syncthreads();

    if (tid < S_) {
        float s0 = 0.f, s1 = 0.f, s2 = 0.f, s3 = 0.f;
        #pragma unroll
        for (int t = 0; t < 16; ++t) {
            s0 += red[0*2048 + t*128 + tid];
            s1 += red[1*2048 + t*128 + tid];
            s2 += red[2*2048 + t*128 + tid];
            s3 += red[3*2048 + t*128 + tid];
        }
        float sigma = fmaxf(s0 + bsig[0], 0.0f);

        float t0 = (float)tid * (1.0f / 127.0f);
        float z0 = NEARV * (1.0f - t0) + FARV * t0;
        float t1 = (float)(tid + 1) * (1.0f / 127.0f);
        float z1 = NEARV * (1.0f - t1) + FARV * t1;
        float alpha = (tid < S_ - 1) ? (1.0f - expf(-sigma * (z1 - z0))) : 1.0f;

        // view-dir rows of Wrgb (dirs = -rd, constant along the ray) + bias
        float e0 = brgb[0] - (d0*Wrgb[(H_+0)*3+0] + d1*Wrgb[(H_+1)*3+0] + d2*Wrgb[(H_+2)*3+0]);
        float e1 = brgb[1] - (d0*Wrgb[(H_+0)*3+1] + d1*Wrgb[(H_+1)*3+1] + d2*Wrgb[(H_+2)*3+1]);
        float e2 = brgb[2] - (d0*Wrgb[(H_+0)*3+2] + d1*Wrgb[(H_+1)*3+2] + d2*Wrgb[(H_+2)*3+2]);

        cbuf[tid]       = alpha;
        cbuf[128 + tid] = 1.0f / (1.0f + expf(-(s1 + e0)));
        cbuf[256 + tid] = 1.0f / (1.0f + expf(-(s2 + e1)));
        cbuf[384 + tid] = 1.0f / (1.0f + expf(-(s3 + e2)));
    }
    __syncthreads();

    // ---- sequential composite (exclusive cumprod of (1 - a + eps)) ----
    if (tid == 0) {
        float T = 1.0f, o0 = 0.f, o1 = 0.f, o2 = 0.f;
        for (int s = 0; s < S_; ++s) {
            float a = cbuf[s];
            float w = a * T;
            o0 = fmaf(w, cbuf[128 + s], o0);
            o1 = fmaf(w, cbuf[256 + s], o1);
            o2 = fmaf(w, cbuf[384 + s], o2);
            T *= (1.0f - a + EPSV);
        }
        out[r*3 + 0] = o0;
        out[r*3 + 1] = o1;
        out[r*3 + 2] = o2;
    }
}

extern "C" void kernel_launch(void* const* d_in, const int* in_sizes, int n_in,
                              void* d_out, int out_size)
{
    const float* cam  = (const float*)d_in[0];
    const float* rayv = (const float*)d_in[1];
    const float* W1   = (const float*)d_in[2];
    const float* b1   = (const float*)d_in[3];
    const float* W2   = (const float*)d_in[4];
    const float* b2   = (const float*)d_in[5];
    const float* Wsig = (const float*)d_in[6];
    const float* bsig = (const float*)d_in[7];
    const float* Wrgb = (const float*)d_in[8];
    const float* brgb = (const float*)d_in[9];
    float* out = (float*)d_out;

    const int nrays = in_sizes[0] / 3;                 // B*N = 4096
    const size_t smem = SMEM_FLOATS * sizeof(float);   // ~199 KB

    cudaFuncSetAttribute(nerf_fused_kernel,
                         cudaFuncAttributeMaxDynamicSharedMemorySize, (int)smem);
    nerf_fused_kernel<<<nrays, 256, smem>>>(cam, rayv, W1, b1, W2, b2,
                                            Wsig, bsig, Wrgb, brgb, out);
}

// round 4
// speedup vs baseline: 5.3147x; 4.8702x over previous
#include <cuda_runtime.h>
#include <cuda_fp16.h>
#include <math.h>
#include <stdint.h>

// NeRF fused renderer, R4: baseline-PTX tensor path (mma.sync m16n8k16 fp16,
// ldmatrix). No sm_103a-specific instructions (harness compiles a compute_103
// PTX pass that rejects tcgen05). 1 ray per CTA, 8 warps, warp tile 32x128.
// W2 staged fully in SMEM (padded stride -> conflict-free ldmatrix rows).

namespace {
constexpr float NEARV = 0.1f, FARV = 4.0f, EPSV = 1e-6f;
constexpr int AS = 264;                      // padded row stride (halves)
constexpr int OFF_A    = 0;                  // h1 tile  [128][AS] fp16
constexpr int OFF_B    = 128 * AS * 2;       // W2 tile  [256][AS] fp16
constexpr int OFF_ACBC = OFF_B + 256 * AS * 2;  // ac[256] | bc[256] fp32
constexpr int OFF_HDW  = OFF_ACBC + 2048;    // float4[256]: Wsig,Wr0,Wr1,Wr2
constexpr int OFF_B2S  = OFF_HDW + 4096;     // float[256]
constexpr int OFF_E    = OFF_B2S + 1024;     // float[4] view-dir consts
constexpr int SMEM_REQ = OFF_E + 16;         // 209952 B
}

__device__ __half g_W2h[256 * 256];          // fp16 W2 image [k][j]

__global__ void prep_w2h(const float* __restrict__ W2) {
    int i = (blockIdx.x * 256 + threadIdx.x) * 4;
    float4 v = *(const float4*)(W2 + i);
    ((__half2*)g_W2h)[i / 2]     = __floats2half2_rn(v.x, v.y);
    ((__half2*)g_W2h)[i / 2 + 1] = __floats2half2_rn(v.z, v.w);
}

__device__ __forceinline__ void ldsm_x4(uint32_t* r, uint32_t a) {
    asm volatile("ldmatrix.sync.aligned.m8n8.x4.shared.b16 {%0,%1,%2,%3}, [%4];"
                 : "=r"(r[0]), "=r"(r[1]), "=r"(r[2]), "=r"(r[3]) : "r"(a));
}
__device__ __forceinline__ void ldsm_x4_t(uint32_t* r, uint32_t a) {
    asm volatile("ldmatrix.sync.aligned.m8n8.x4.trans.shared.b16 {%0,%1,%2,%3}, [%4];"
                 : "=r"(r[0]), "=r"(r[1]), "=r"(r[2]), "=r"(r[3]) : "r"(a));
}
__device__ __forceinline__ void mma16816(float* c, const uint32_t* a,
                                         const uint32_t* b) {
    asm volatile(
        "mma.sync.aligned.m16n8k16.row.col.f32.f16.f16.f32 "
        "{%0,%1,%2,%3}, {%4,%5,%6,%7}, {%8,%9}, {%0,%1,%2,%3};"
        : "+f"(c[0]), "+f"(c[1]), "+f"(c[2]), "+f"(c[3])
        : "r"(a[0]), "r"(a[1]), "r"(a[2]), "r"(a[3]), "r"(b[0]), "r"(b[1]));
}

__global__ __launch_bounds__(256, 1)
void nerf_mma_kernel(const float* __restrict__ cam,
                     const float* __restrict__ rayv,
                     const float* __restrict__ W1,
                     const float* __restrict__ b1,
                     const float* __restrict__ b2,
                     const float* __restrict__ Wsig,
                     const float* __restrict__ bsig,
                     const float* __restrict__ Wrgb,
                     const float* __restrict__ brgb,
                     float* __restrict__ out)
{
    extern __shared__ char smem[];
    uint32_t smb;
    asm("{ .reg .u64 t; cvta.to.shared.u64 t, %1; cvt.u32.u64 %0, t; }"
        : "=r"(smb) : "l"(smem));

    const int tid = threadIdx.x, r = blockIdx.x;

    // ---- geometry ----
    const float v0 = rayv[r*3+0], v1 = rayv[r*3+1], v2 = rayv[r*3+2];
    const float inv = rsqrtf(v0*v0 + v1*v1 + v2*v2);
    const float d0 = v0*inv, d1 = v1*inv, d2 = v2*inv;
    const float c0 = cam[r*3+0], c1 = cam[r*3+1], c2 = cam[r*3+2];

    // ---- tables (k = tid) ----
    {
        int k = tid;
        float w0 = W1[k], w1 = W1[256 + k], w2 = W1[512 + k];
        float* acbc = (float*)(smem + OFF_ACBC);
        acbc[k]       = c0*w0 + c1*w1 + c2*w2 + b1[k];
        acbc[256 + k] = d0*w0 + d1*w1 + d2*w2;
        ((float4*)(smem + OFF_HDW))[k] =
            make_float4(Wsig[k], Wrgb[k*3+0], Wrgb[k*3+1], Wrgb[k*3+2]);
        ((float*)(smem + OFF_B2S))[k] = b2[k];
    }
    if (tid < 3) {
        float* e = (float*)(smem + OFF_E);
        e[tid] = brgb[tid] - (d0 * Wrgb[(256+0)*3 + tid] +
                              d1 * Wrgb[(256+1)*3 + tid] +
                              d2 * Wrgb[(256+2)*3 + tid]);
    }

    // ---- stage W2 fp16 into padded SMEM (8 halves per 16B chunk) ----
    {
        const uint4* src = (const uint4*)g_W2h;
        #pragma unroll
        for (int it = 0; it < 32; ++it) {
            int idx = tid + it * 256;          // 8192 chunks
            int row = idx >> 5, c = idx & 31;
            *(uint4*)(smem + OFF_B + (row * AS + c * 8) * 2) = src[idx];
        }
    }
    __syncthreads();  // acbc ready

    // ---- h1 tile: relu(ac + bc*z_p) -> fp16, thread owns (p, k-half) ----
    {
        int p = tid >> 1, kh = (tid & 1) * 128;
        float t = (float)p * (1.0f / 127.0f);
        float zp = NEARV * (1.0f - t) + FARV * t;
        const float* ac = (const float*)(smem + OFF_ACBC);
        const float* bc = ac + 256;
        __half* arow = (__half*)(smem + OFF_A) + p * AS;
        #pragma unroll 8
        for (int k = 0; k < 128; k += 2) {
            float h0 = fmaxf(fmaf(bc[kh+k],   zp, ac[kh+k]),   0.0f);
            float h1 = fmaxf(fmaf(bc[kh+k+1], zp, ac[kh+k+1]), 0.0f);
            *(__half2*)(arow + kh + k) = __floats2half2_rn(h0, h1);
        }
    }
    __syncthreads();

    // ---- mainloop: warp (wm, wn) computes points [wm*32,+32) x j [wn*128,+128)
    const int w = tid >> 5, lane = tid & 31;
    const int wm = w & 3, wn = w >> 2;
    const int m0 = wm * 32, n0 = wn * 128;

    uint32_t a_addr0 = smb + OFF_A + ((m0 + (lane & 15)) * AS + (lane >> 4) * 8) * 2;
    uint32_t a_addr1 = a_addr0 + 16 * AS * 2;
    const int krow = (lane & 7) + ((lane >> 3) & 1) * 8;
    const int bcol = (lane >> 4) * 8;
    uint32_t b_addr[8];
    #pragma unroll
    for (int nf2 = 0; nf2 < 8; ++nf2)
        b_addr[nf2] = smb + OFF_B + (krow * AS + n0 + nf2 * 16 + bcol) * 2;

    float acc[2][16][4];
    #pragma unroll
    for (int mf = 0; mf < 2; ++mf)
        #pragma unroll
        for (int nf = 0; nf < 16; ++nf)
            #pragma unroll
            for (int q = 0; q < 4; ++q) acc[mf][nf][q] = 0.0f;

    #pragma unroll
    for (int ks = 0; ks < 16; ++ks) {
        uint32_t a0[4], a1[4];
        ldsm_x4(a0, a_addr0 + ks * 32);
        ldsm_x4(a1, a_addr1 + ks * 32);
        #pragma unroll
        for (int nf2 = 0; nf2 < 8; ++nf2) {
            uint32_t b[4];
            ldsm_x4_t(b, b_addr[nf2] + ks * 16 * AS * 2);
            mma16816(acc[0][nf2*2],     a0, b);
            mma16816(acc[0][nf2*2 + 1], a0, b + 2);
            mma16816(acc[1][nf2*2],     a1, b);
            mma16816(acc[1][nf2*2 + 1], a1, b + 2);
        }
    }

    // ---- fused epilogue: relu(h2+b2) projected onto 4 heads, per point ----
    __syncthreads();                       // all warps done reading B
    float* red = (float*)(smem + OFF_B);   // alias: [128 pts][4 heads][8 slots]
    const float* b2s = (const float*)(smem + OFF_B2S);
    const float4* hdw = (const float4*)(smem + OFF_HDW);
    const int q = lane & 3, rowb = lane >> 2;

    float s[4][4];
    #pragma unroll
    for (int i = 0; i < 4; ++i)
        #pragma unroll
        for (int h = 0; h < 4; ++h) s[i][h] = 0.0f;

    #pragma unroll
    for (int mf = 0; mf < 2; ++mf)
        #pragma unroll
        for (int nf = 0; nf < 16; ++nf) {
            int j0 = n0 + nf * 8 + q * 2;
            float bb0 = b2s[j0], bb1 = b2s[j0 + 1];
            float4 w0v = hdw[j0], w1v = hdw[j0 + 1];
            float h00 = fmaxf(acc[mf][nf][0] + bb0, 0.0f);
            float h01 = fmaxf(acc[mf][nf][1] + bb1, 0.0f);
            float h10 = fmaxf(acc[mf][nf][2] + bb0, 0.0f);
            float h11 = fmaxf(acc[mf][nf][3] + bb1, 0.0f);
            s[mf*2][0]   = fmaf(h00, w0v.x, fmaf(h01, w1v.x, s[mf*2][0]));
            s[mf*2][1]   = fmaf(h00, w0v.y, fmaf(h01, w1v.y, s[mf*2][1]));
            s[mf*2][2]   = fmaf(h00, w0v.z, fmaf(h01, w1v.z, s[mf*2][2]));
            s[mf*2][3]   = fmaf(h00, w0v.w, fmaf(h01, w1v.w, s[mf*2][3]));
            s[mf*2+1][0] = fmaf(h10, w0v.x, fmaf(h11, w1v.x, s[mf*2+1][0]));
            s[mf*2+1][1] = fmaf(h10, w0v.y, fmaf(h11, w1v.y, s[mf*2+1][1]));
            s[mf*2+1][2] = fmaf(h10, w0v.z, fmaf(h11, w1v.z, s[mf*2+1][2]));
            s[mf*2+1][3] = fmaf(h10, w0v.w, fmaf(h11, w1v.w, s[mf*2+1][3]));
        }

    const int slot = wn * 4 + q;
    #pragma unroll
    for (int pt = 0; pt < 4; ++pt) {
        int p = m0 + (pt >> 1) * 16 + rowb + (pt & 1) * 8;
        #pragma unroll
        for (int h = 0; h < 4; ++h)
            red[(p * 4 + h) * 8 + slot] = s[pt][h];
    }
    __syncthreads();

    float* cbuf = red + 4096;             // [a|r|g|b][128]
    if (tid < 128) {
        float sum0 = 0.f, sum1 = 0.f, sum2 = 0.f, sum3 = 0.f;
        #pragma unroll
        for (int sl = 0; sl < 8; ++sl) {
            sum0 += red[(tid * 4 + 0) * 8 + sl];
            sum1 += red[(tid * 4 + 1) * 8 + sl];
            sum2 += red[(tid * 4 + 2) * 8 + sl];
            sum3 += red[(tid * 4 + 3) * 8 + sl];
        }
        float sigma = fmaxf(sum0 + bsig[0], 0.0f);
        float t0 = (float)tid * (1.0f / 127.0f);
        float z0 = NEARV * (1.0f - t0) + FARV * t0;
        float t1 = (float)(tid + 1) * (1.0f / 127.0f);
        float z1 = NEARV * (1.0f - t1) + FARV * t1;
        float alpha = (tid < 127) ? (1.0f - expf(-sigma * (z1 - z0))) : 1.0f;
        const float* e = (const float*)(smem + OFF_E);
        cbuf[tid]       = alpha;
        cbuf[128 + tid] = 1.0f / (1.0f + expf(-(sum1 + e[0])));
        cbuf[256 + tid] = 1.0f / (1.0f + expf(-(sum2 + e[1])));
        cbuf[384 + tid] = 1.0f / (1.0f + expf(-(sum3 + e[2])));
    }
    __syncthreads();

    if (tid == 0) {
        float T = 1.0f, o0 = 0.f, o1 = 0.f, o2 = 0.f;
        for (int sidx = 0; sidx < 128; ++sidx) {
            float a = cbuf[sidx];
            float wgt = a * T;
            o0 = fmaf(wgt, cbuf[128 + sidx], o0);
            o1 = fmaf(wgt, cbuf[256 + sidx], o1);
            o2 = fmaf(wgt, cbuf[384 + sidx], o2);
            T *= (1.0f - a + EPSV);
        }
        out[r*3 + 0] = o0;
        out[r*3 + 1] = o1;
        out[r*3 + 2] = o2;
    }
}

extern "C" void kernel_launch(void* const* d_in, const int* in_sizes, int n_in,
                              void* d_out, int out_size)
{
    const float* cam  = (const float*)d_in[0];
    const float* rayv = (const float*)d_in[1];
    const float* W1   = (const float*)d_in[2];
    const float* b1   = (const float*)d_in[3];
    const float* W2   = (const float*)d_in[4];
    const float* b2   = (const float*)d_in[5];
    const float* Wsig = (const float*)d_in[6];
    const float* bsig = (const float*)d_in[7];
    const float* Wrgb = (const float*)d_in[8];
    const float* brgb = (const float*)d_in[9];
    float* out = (float*)d_out;

    const int nrays = in_sizes[0] / 3;   // 4096

    prep_w2h<<<64, 256>>>(W2);

    cudaFuncSetAttribute(nerf_mma_kernel,
                         cudaFuncAttributeMaxDynamicSharedMemorySize, SMEM_REQ);
    nerf_mma_kernel<<<nrays, 256, SMEM_REQ>>>(cam, rayv, W1, b1, b2,
                                              Wsig, bsig, Wrgb, brgb, out);
}

// round 5
// speedup vs baseline: 7.2272x; 1.3599x over previous
#include <cuda_runtime.h>
#include <cuda_fp16.h>
#include <math.h>
#include <stdint.h>

// NeRF fused renderer, R5: 2 rays/CTA joint M=256 GEMM, A-fragments computed
// in registers (no A tile, no A LDSM), warp tile 64x64 with two N-passes.
// B (W2 fp16) staged once per CTA, padded stride (conflict-free ldmatrix).

namespace {
constexpr float NEARV = 0.1f, FARV = 4.0f, EPSV = 1e-6f;
constexpr int AS = 264;                        // B row stride in halves
constexpr int OFF_B     = 0;                   // [256k][AS] fp16 = 135168 B
constexpr int OFF_ACBC4 = 135168;              // float4[2][128]: ac,bc pairs
constexpr int OFF_HDW   = OFF_ACBC4 + 4096;    // float4[256]: Wsig,Wr0,Wr1,Wr2
constexpr int OFF_B2S   = OFF_HDW + 4096;      // float[256]
constexpr int OFF_E     = OFF_B2S + 1024;      // float[8]: 2 rays x 3 + pad
constexpr int OFF_CBUF  = OFF_E + 32;          // float[2][4][128]
constexpr int SMEM_REQ  = OFF_CBUF + 4096;     // 148512 B
}

__device__ __half g_W2h[256 * 256];            // fp16 W2 [k][j]

__global__ void prep_w2h(const float* __restrict__ W2) {
    int i = (blockIdx.x * 256 + threadIdx.x) * 4;
    float4 v = *(const float4*)(W2 + i);
    ((__half2*)g_W2h)[i / 2]     = __floats2half2_rn(v.x, v.y);
    ((__half2*)g_W2h)[i / 2 + 1] = __floats2half2_rn(v.z, v.w);
}

__device__ __forceinline__ void ldsm_x4_t(uint32_t* r, uint32_t a) {
    asm volatile("ldmatrix.sync.aligned.m8n8.x4.trans.shared.b16 {%0,%1,%2,%3}, [%4];"
                 : "=r"(r[0]), "=r"(r[1]), "=r"(r[2]), "=r"(r[3]) : "r"(a));
}
__device__ __forceinline__ void mma16816(float* c, const uint32_t* a,
                                         const uint32_t* b) {
    asm volatile(
        "mma.sync.aligned.m16n8k16.row.col.f32.f16.f16.f32 "
        "{%0,%1,%2,%3}, {%4,%5,%6,%7}, {%8,%9}, {%0,%1,%2,%3};"
        : "+f"(c[0]), "+f"(c[1]), "+f"(c[2]), "+f"(c[3])
        : "r"(a[0]), "r"(a[1]), "r"(a[2]), "r"(a[3]), "r"(b[0]), "r"(b[1]));
}
__device__ __forceinline__ uint32_t pack2(float lo, float hi) {
    __half2 h = __floats2half2_rn(lo, hi);
    return *(uint32_t*)&h;
}

__global__ __launch_bounds__(256, 1)
void nerf_mma2_kernel(const float* __restrict__ cam,
                      const float* __restrict__ rayv,
                      const float* __restrict__ W1,
                      const float* __restrict__ b1,
                      const float* __restrict__ b2,
                      const float* __restrict__ Wsig,
                      const float* __restrict__ bsig,
                      const float* __restrict__ Wrgb,
                      const float* __restrict__ brgb,
                      float* __restrict__ out)
{
    extern __shared__ char smem[];
    uint32_t smb;
    asm("{ .reg .u64 t; cvta.to.shared.u64 t, %1; cvt.u32.u64 %0, t; }"
        : "=r"(smb) : "l"(smem));

    const int tid = threadIdx.x;
    const int r0 = blockIdx.x * 2;

    // ---- geometry for both rays ----
    float dx[2], dy[2], dz[2];
    #pragma unroll
    for (int rr = 0; rr < 2; ++rr) {
        float v0 = rayv[(r0+rr)*3+0], v1 = rayv[(r0+rr)*3+1], v2 = rayv[(r0+rr)*3+2];
        float inv = rsqrtf(v0*v0 + v1*v1 + v2*v2);
        dx[rr] = v0*inv; dy[rr] = v1*inv; dz[rr] = v2*inv;
    }

    // ---- stage B (W2 fp16) into padded SMEM ----
    {
        const uint4* src = (const uint4*)g_W2h;
        #pragma unroll
        for (int it = 0; it < 32; ++it) {
            int idx = tid + it * 256;
            int row = idx >> 5, c = idx & 31;
            *(uint4*)(smem + OFF_B + (row * AS + c * 8) * 2) = src[idx];
        }
    }
    // ---- tables ----
    {
        int k = tid;
        ((float4*)(smem + OFF_HDW))[k] =
            make_float4(Wsig[k], Wrgb[k*3+0], Wrgb[k*3+1], Wrgb[k*3+2]);
        ((float*)(smem + OFF_B2S))[k] = b2[k];
    }
    if (tid < 128) {                       // k-pair tables for both rays
        int k0 = tid * 2;
        float w00 = W1[k0],     w10 = W1[256+k0],   w20 = W1[512+k0],   bb0 = b1[k0];
        float w01 = W1[k0+1],   w11 = W1[256+k0+1], w21 = W1[512+k0+1], bb1 = b1[k0+1];
        #pragma unroll
        for (int rr = 0; rr < 2; ++rr) {
            float cc0 = cam[(r0+rr)*3+0], cc1 = cam[(r0+rr)*3+1], cc2 = cam[(r0+rr)*3+2];
            float ac0 = cc0*w00 + cc1*w10 + cc2*w20 + bb0;
            float bc0 = dx[rr]*w00 + dy[rr]*w10 + dz[rr]*w20;
            float ac1 = cc0*w01 + cc1*w11 + cc2*w21 + bb1;
            float bc1 = dx[rr]*w01 + dy[rr]*w11 + dz[rr]*w21;
            ((float4*)(smem + OFF_ACBC4))[rr * 128 + tid] =
                make_float4(ac0, bc0, ac1, bc1);
        }
    }
    if (tid < 6) {                         // per-ray view-dir consts
        int rr = tid / 3, t = tid % 3;
        ((float*)(smem + OFF_E))[rr * 4 + t] =
            brgb[t] - (dx[rr] * Wrgb[(256+0)*3 + t] +
                       dy[rr] * Wrgb[(256+1)*3 + t] +
                       dz[rr] * Wrgb[(256+2)*3 + t]);
    }
    __syncthreads();

    // ---- warp mapping: 8 warps = (wm 0..3) x (wn 0..1); warp ray = wm>>1 ----
    const int w = tid >> 5, lane = tid & 31;
    const int wm = w & 3, wn = w >> 1 & 2 ? 0 : 0;  // placeholder (fixed below)
    const int wn_ = w >> 2;                          // 0..1
    const int ray = wm >> 1;
    const int q = lane & 3, rowq = lane >> 2;

    // z for this thread's 8 rows (mf 0..3 x {0,+8})
    float zr[8];
    #pragma unroll
    for (int i = 0; i < 8; ++i) {
        int m = wm * 64 + (i >> 1) * 16 + rowq + (i & 1) * 8;
        int p = m & 127;
        float t = (float)p * (1.0f / 127.0f);
        zr[i] = NEARV * (1.0f - t) + FARV * t;
    }
    const float4* acbc = (const float4*)(smem + OFF_ACBC4) + ray * 128;

    // B ldsm lane address parts
    const int krow = lane & 15, bcol = (lane >> 4) * 8;

    // head partial sums: 8 rows x 4 heads
    float s[8][4];
    #pragma unroll
    for (int i = 0; i < 8; ++i)
        #pragma unroll
        for (int h = 0; h < 4; ++h) s[i][h] = 0.0f;

    const float* b2s = (const float*)(smem + OFF_B2S);
    const float4* hdw = (const float4*)(smem + OFF_HDW);

    #pragma unroll
    for (int pp = 0; pp < 2; ++pp) {
        const int n0 = pp * 128 + wn_ * 64;
        uint32_t baddr[4];
        #pragma unroll
        for (int nf2 = 0; nf2 < 4; ++nf2)
            baddr[nf2] = smb + OFF_B + (krow * AS + n0 + nf2 * 16 + bcol) * 2;

        float acc[4][8][4];
        #pragma unroll
        for (int mf = 0; mf < 4; ++mf)
            #pragma unroll
            for (int nf = 0; nf < 8; ++nf)
                #pragma unroll
                for (int c = 0; c < 4; ++c) acc[mf][nf][c] = 0.0f;

        #pragma unroll 4
        for (int ks = 0; ks < 16; ++ks) {
            // A fragments from registers: h = relu(ac + bc*z)
            int kidx = ks * 8 + q;                  // float4 index (k pair)
            float4 lo = acbc[kidx];                 // ac,bc for k0,k0+1
            float4 hi = acbc[kidx + 4];             // ac,bc for k0+8,k0+9
            uint32_t a[4][4];
            #pragma unroll
            for (int mf = 0; mf < 4; ++mf) {
                float z0 = zr[mf * 2], z1 = zr[mf * 2 + 1];
                a[mf][0] = pack2(fmaxf(fmaf(lo.y, z0, lo.x), 0.0f),
                                 fmaxf(fmaf(lo.w, z0, lo.z), 0.0f));
                a[mf][1] = pack2(fmaxf(fmaf(lo.y, z1, lo.x), 0.0f),
                                 fmaxf(fmaf(lo.w, z1, lo.z), 0.0f));
                a[mf][2] = pack2(fmaxf(fmaf(hi.y, z0, hi.x), 0.0f),
                                 fmaxf(fmaf(hi.w, z0, hi.z), 0.0f));
                a[mf][3] = pack2(fmaxf(fmaf(hi.y, z1, hi.x), 0.0f),
                                 fmaxf(fmaf(hi.w, z1, hi.z), 0.0f));
            }
            #pragma unroll
            for (int nf2 = 0; nf2 < 4; ++nf2) {
                uint32_t b[4];
                ldsm_x4_t(b, baddr[nf2] + ks * (16 * AS * 2));
                #pragma unroll
                for (int mf = 0; mf < 4; ++mf) {
                    mma16816(acc[mf][nf2*2],     a[mf], b);
                    mma16816(acc[mf][nf2*2 + 1], a[mf], b + 2);
                }
            }
        }

        // fold this pass into head partials: relu(h2+b2) . {Wsig,Wrgb}
        #pragma unroll
        for (int nf = 0; nf < 8; ++nf) {
            int j0 = n0 + nf * 8 + q * 2;
            float bb0 = b2s[j0], bb1 = b2s[j0 + 1];
            float4 w0v = hdw[j0], w1v = hdw[j0 + 1];
            #pragma unroll
            for (int mf = 0; mf < 4; ++mf) {
                float h00 = fmaxf(acc[mf][nf][0] + bb0, 0.0f);
                float h01 = fmaxf(acc[mf][nf][1] + bb1, 0.0f);
                float h10 = fmaxf(acc[mf][nf][2] + bb0, 0.0f);
                float h11 = fmaxf(acc[mf][nf][3] + bb1, 0.0f);
                s[mf*2][0]   = fmaf(h00, w0v.x, fmaf(h01, w1v.x, s[mf*2][0]));
                s[mf*2][1]   = fmaf(h00, w0v.y, fmaf(h01, w1v.y, s[mf*2][1]));
                s[mf*2][2]   = fmaf(h00, w0v.z, fmaf(h01, w1v.z, s[mf*2][2]));
                s[mf*2][3]   = fmaf(h00, w0v.w, fmaf(h01, w1v.w, s[mf*2][3]));
                s[mf*2+1][0] = fmaf(h10, w0v.x, fmaf(h11, w1v.x, s[mf*2+1][0]));
                s[mf*2+1][1] = fmaf(h10, w0v.y, fmaf(h11, w1v.y, s[mf*2+1][1]));
                s[mf*2+1][2] = fmaf(h10, w0v.z, fmaf(h11, w1v.z, s[mf*2+1][2]));
                s[mf*2+1][3] = fmaf(h10, w0v.w, fmaf(h11, w1v.w, s[mf*2+1][3]));
            }
        }
    }

    // ---- slot reduction: red[m][slot(8, padded to 9)][head4] aliases B ----
    __syncthreads();                       // all B reads done
    float* red = (float*)(smem + OFF_B);   // 256 * 9 * 16B = 36864 B
    const int slot = wn_ * 4 + q;
    #pragma unroll
    for (int i = 0; i < 8; ++i) {
        int m = wm * 64 + (i >> 1) * 16 + rowq + (i & 1) * 8;
        *(float4*)(red + (m * 9 + slot) * 4) =
            make_float4(s[i][0], s[i][1], s[i][2], s[i][3]);
    }
    __syncthreads();

    float* cbuf = (float*)(smem + OFF_CBUF);
    {
        int m = tid;                       // 256 threads = 256 (ray,p)
        float4 t0 = *(float4*)(red + (m * 9 + 0) * 4);
        #pragma unroll
        for (int sl = 1; sl < 8; ++sl) {
            float4 t = *(float4*)(red + (m * 9 + sl) * 4);
            t0.x += t.x; t0.y += t.y; t0.z += t.z; t0.w += t.w;
        }
        int rr = m >> 7, p = m & 127;
        float sigma = fmaxf(t0.x + bsig[0], 0.0f);
        float ta = (float)p * (1.0f / 127.0f);
        float z0 = NEARV * (1.0f - ta) + FARV * ta;
        float tb = (float)(p + 1) * (1.0f / 127.0f);
        float z1 = NEARV * (1.0f - tb) + FARV * tb;
        float alpha = (p < 127) ? (1.0f - expf(-sigma * (z1 - z0))) : 1.0f;
        const float* e = (const float*)(smem + OFF_E) + rr * 4;
        float* cb = cbuf + rr * 512;
        cb[p]       = alpha;
        cb[128 + p] = 1.0f / (1.0f + expf(-(t0.y + e[0])));
        cb[256 + p] = 1.0f / (1.0f + expf(-(t0.z + e[1])));
        cb[384 + p] = 1.0f / (1.0f + expf(-(t0.w + e[2])));
    }
    __syncthreads();

    if (tid < 2) {
        const float* cb = cbuf + tid * 512;
        float T = 1.0f, o0 = 0.f, o1 = 0.f, o2 = 0.f;
        for (int sidx = 0; sidx < 128; ++sidx) {
            float a = cb[sidx];
            float wgt = a * T;
            o0 = fmaf(wgt, cb[128 + sidx], o0);
            o1 = fmaf(wgt, cb[256 + sidx], o1);
            o2 = fmaf(wgt, cb[384 + sidx], o2);
            T *= (1.0f - a + EPSV);
        }
        out[(r0 + tid) * 3 + 0] = o0;
        out[(r0 + tid) * 3 + 1] = o1;
        out[(r0 + tid) * 3 + 2] = o2;
    }
}

extern "C" void kernel_launch(void* const* d_in, const int* in_sizes, int n_in,
                              void* d_out, int out_size)
{
    const float* cam  = (const float*)d_in[0];
    const float* rayv = (const float*)d_in[1];
    const float* W1   = (const float*)d_in[2];
    const float* b1   = (const float*)d_in[3];
    const float* W2   = (const float*)d_in[4];
    const float* b2   = (const float*)d_in[5];
    const float* Wsig = (const float*)d_in[6];
    const float* bsig = (const float*)d_in[7];
    const float* Wrgb = (const float*)d_in[8];
    const float* brgb = (const float*)d_in[9];
    float* out = (float*)d_out;

    const int nrays = in_sizes[0] / 3;     // 4096

    prep_w2h<<<64, 256>>>(W2);

    cudaFuncSetAttribute(nerf_mma2_kernel,
                         cudaFuncAttributeMaxDynamicSharedMemorySize, SMEM_REQ);
    nerf_mma2_kernel<<<nrays / 2, 256, SMEM_REQ>>>(cam, rayv, W1, b1, b2,
                                                   Wsig, bsig, Wrgb, brgb, out);
}